// round 13
// baseline (speedup 1.0000x reference)
#include <cuda_runtime.h>
#include <cuda_fp16.h>
#include <math_constants.h>
#include <cstdint>

// ---------------- problem constants ----------------
#define NN 16384      // nodes
#define GG 256        // graphs
#define NPG 64        // nodes per graph
#define FF 64         // per-head features
#define DD 512        // H*F
#define NTOT 1024     // fused Wl|Wr output width
#define EMAX 147456

// ---------------- scratch ----------------
__device__ __half g_XLR0[NN * NTOT];    // ping
__device__ __half g_XLR1[NN * NTOT];    // pong
__device__ __half g_Xh[NN * 256];
__device__ __half g_Bh[NN * DD];
__device__ __half g_Wh[1310720];
__device__ int    g_cnt [NN];
__device__ int    g_row [NN + 1];
__device__ int    g_fill[NN];
__device__ int    g_csrc[EMAX];

// ---------------- helpers ----------------
__device__ __forceinline__ uint32_t smem_u32(const void* p) {
    return (uint32_t)__cvta_generic_to_shared(p);
}
__device__ __forceinline__ void cp16(uint32_t d, const void* s) {
    asm volatile("cp.async.cg.shared.global [%0], [%1], 16;" :: "r"(d), "l"(s));
}

// ---------------- prep kernels ----------------
__global__ void to_half_kernel(const float4* __restrict__ in, __half2* __restrict__ out, int n4) {
    int i = blockIdx.x * blockDim.x + threadIdx.x;
    if (i < n4) {
        float4 v = in[i];
        out[i * 2]     = __floats2half2_rn(v.x, v.y);
        out[i * 2 + 1] = __floats2half2_rn(v.z, v.w);
    }
}

__global__ void transpose_all_kernel(const float* __restrict__ W0, const float* __restrict__ W1,
                                     const float* __restrict__ W2, const float* __restrict__ W3,
                                     const float* __restrict__ W4, const float* __restrict__ W5,
                                     __half* __restrict__ Wh) {
    __shared__ float t[32][33];
    const int z = blockIdx.z;
    const int K = (z < 2) ? 256 : 512;
    const int by = blockIdx.y * 32;
    if (by >= K) return;
    const float* W;
    uint32_t off;
    switch (z) {
        case 0: W = W0; off = 0u;       break;
        case 1: W = W1; off = 131072u;  break;
        case 2: W = W2; off = 262144u;  break;
        case 3: W = W3; off = 524288u;  break;
        case 4: W = W4; off = 786432u;  break;
        default:W = W5; off = 1048576u; break;
    }
    __half* Wt = Wh + off;
    const int bx = blockIdx.x * 32;
    const int x = threadIdx.x, y = threadIdx.y;
#pragma unroll
    for (int j = 0; j < 32; j += 8) t[y + j][x] = W[(size_t)(by + y + j) * DD + bx + x];
    __syncthreads();
#pragma unroll
    for (int j = 0; j < 32; j += 8)
        Wt[(size_t)(bx + y + j) * K + by + x] = __float2half_rn(t[x][y + j]);
}

// ---------------- CSR build ----------------
__global__ void zero_int_kernel(int* p, int n) {
    int i = blockIdx.x * blockDim.x + threadIdx.x;
    if (i < n) p[i] = 0;
}
__global__ void count_kernel(const int* __restrict__ dst, int E, int* __restrict__ cnt) {
    int e = blockIdx.x * blockDim.x + threadIdx.x;
    if (e < E) atomicAdd(&cnt[dst[e]], 1);
}
__global__ void scan_kernel(const int* __restrict__ cnt, int* __restrict__ row,
                            int* __restrict__ fill) {
    __shared__ int s[1024];
    int tid = threadIdx.x;
    int base = tid * 16;
    int local[16];
    int sum = 0;
#pragma unroll
    for (int i = 0; i < 16; i++) { local[i] = sum; sum += cnt[base + i]; }
    s[tid] = sum;
    __syncthreads();
    for (int off = 1; off < 1024; off <<= 1) {
        int v = (tid >= off) ? s[tid - off] : 0;
        __syncthreads();
        s[tid] += v;
        __syncthreads();
    }
    int pre = (tid == 0) ? 0 : s[tid - 1];
#pragma unroll
    for (int i = 0; i < 16; i++) {
        int o = pre + local[i];
        row[base + i]  = o;
        fill[base + i] = o;
    }
    if (tid == 1023) row[NN] = s[1023];
}
__global__ void scatter_kernel(const int* __restrict__ src, const int* __restrict__ dst,
                               int E, int* __restrict__ fill, int* __restrict__ csrc) {
    int e = blockIdx.x * blockDim.x + threadIdx.x;
    if (e < E) {
        int p = atomicAdd(&fill[dst[e]], 1);
        csrc[p] = src[e];
    }
}

// ---------------- fp16 GEMM (M-half capable): C[M,1024] = A @ W^T, fp16 out ----------------
#define STAGE_BYTES 20480u
#define GEMM_SMEM   (3u * STAGE_BYTES)

__global__ __launch_bounds__(256, 2)
void hgemm_kernel(int K, int mOff, const __half* __restrict__ A,
                  const __half* __restrict__ W, __half* __restrict__ C) {
    extern __shared__ __align__(16) char smem[];
    const uint32_t sb = smem_u32(smem);

    const int tid = threadIdx.x, lane = tid & 31, warp = tid >> 5;
    const int wm = (warp >> 2) << 6;
    const int wn = (warp & 3) << 5;
    const int bm = (blockIdx.y + mOff) << 7, bn = blockIdx.x << 7;

    const int r = tid >> 1, sc = (tid & 1) << 4;
    const __half* Ag = A + (size_t)(bm + r) * K + sc;
    const __half* Wg = W + (size_t)(bn + r) * K + sc;
    const uint32_t dA = sb + (uint32_t)(r * 40 + sc) * 2;
    const uint32_t dB = sb + 10240u + (uint32_t)(r * 40 + sc) * 2;

#define LOADSTAGE(s, kt) do {                                    \
        uint32_t _k = (uint32_t)(kt) << 5;                       \
        cp16(dA + (s) * STAGE_BYTES,       Ag + _k);             \
        cp16(dA + (s) * STAGE_BYTES + 16u, Ag + _k + 8);         \
        cp16(dB + (s) * STAGE_BYTES,       Wg + _k);             \
        cp16(dB + (s) * STAGE_BYTES + 16u, Wg + _k + 8);         \
        asm volatile("cp.async.commit_group;" ::: "memory");     \
    } while (0)

    float c[4][4][4] = {};

    const int aRow  = wm + (lane & 15);
    const int aColH = (lane >> 4) << 3;
    const int bRow0 = wn + ((lane >> 4) << 3) + (lane & 7);
    const int bColH = ((lane >> 3) & 1) << 3;

    LOADSTAGE(0, 0);
    LOADSTAGE(1, 1);

    const int KT = K >> 5;
    int s = 0;
    for (int kt = 0; kt < KT; kt++) {
        asm volatile("cp.async.wait_group 1;" ::: "memory");
        __syncthreads();

        if (kt + 2 < KT) {
            int sn = (s + 2 >= 3) ? s - 1 : s + 2;
            LOADSTAGE(sn, kt + 2);
        } else {
            asm volatile("cp.async.commit_group;" ::: "memory");
        }

        const uint32_t aBase = sb + s * STAGE_BYTES;
        const uint32_t bBase = aBase + 10240u;
#pragma unroll
        for (int ks = 0; ks < 2; ks++) {
            uint32_t a[4][4];
#pragma unroll
            for (int mt = 0; mt < 4; mt++) {
                uint32_t addr = aBase + (uint32_t)((aRow + mt * 16) * 40 + ks * 16 + aColH) * 2;
                asm volatile("ldmatrix.sync.aligned.m8n8.x4.shared.b16 {%0,%1,%2,%3}, [%4];"
                    : "=r"(a[mt][0]), "=r"(a[mt][1]), "=r"(a[mt][2]), "=r"(a[mt][3])
                    : "r"(addr));
            }
            uint32_t b[2][4];
#pragma unroll
            for (int p = 0; p < 2; p++) {
                uint32_t addr = bBase + (uint32_t)((bRow0 + p * 16) * 40 + ks * 16 + bColH) * 2;
                asm volatile("ldmatrix.sync.aligned.m8n8.x4.shared.b16 {%0,%1,%2,%3}, [%4];"
                    : "=r"(b[p][0]), "=r"(b[p][1]), "=r"(b[p][2]), "=r"(b[p][3])
                    : "r"(addr));
            }
#pragma unroll
            for (int mt = 0; mt < 4; mt++)
#pragma unroll
                for (int nt = 0; nt < 4; nt++) {
                    const uint32_t b0 = b[nt >> 1][(nt & 1) * 2];
                    const uint32_t b1 = b[nt >> 1][(nt & 1) * 2 + 1];
                    asm volatile(
                        "mma.sync.aligned.m16n8k16.row.col.f32.f16.f16.f32 "
                        "{%0,%1,%2,%3},{%4,%5,%6,%7},{%8,%9},{%0,%1,%2,%3};"
                        : "+f"(c[mt][nt][0]), "+f"(c[mt][nt][1]),
                          "+f"(c[mt][nt][2]), "+f"(c[mt][nt][3])
                        : "r"(a[mt][0]), "r"(a[mt][1]), "r"(a[mt][2]), "r"(a[mt][3]),
                          "r"(b0), "r"(b1));
                }
        }
        s = (s + 1 >= 3) ? 0 : s + 1;
    }
#undef LOADSTAGE

    const int g = lane >> 2, t = lane & 3;
#pragma unroll
    for (int mt = 0; mt < 4; mt++) {
        int r0 = bm + wm + mt * 16 + g;
#pragma unroll
        for (int nt = 0; nt < 4; nt++) {
            int col = bn + wn + nt * 8 + 2 * t;
            *(__half2*)(C + (size_t)r0 * NTOT + col) =
                __floats2half2_rn(c[mt][nt][0], c[mt][nt][1]);
            *(__half2*)(C + (size_t)(r0 + 8) * NTOT + col) =
                __floats2half2_rn(c[mt][nt][2], c[mt][nt][3]);
        }
    }
}

// ---------------- per-warp GATv2 agg for one node (half2 logit path) ----------------
__device__ __forceinline__ void agg_node(const __half* __restrict__ xlr, int node,
                                         const int* __restrict__ row, const int* __restrict__ csrc,
                                         const __half2* att2, int fb, float* res) {
    __half2 xr2[8];
    {
        const uint4* rp = (const uint4*)(xlr + (size_t)node * NTOT + 512 + fb);
#pragma unroll
        for (int q = 0; q < 2; q++) {
            uint4 v = rp[q];
            xr2[q * 4 + 0] = *(__half2*)&v.x;
            xr2[q * 4 + 1] = *(__half2*)&v.y;
            xr2[q * 4 + 2] = *(__half2*)&v.z;
            xr2[q * 4 + 3] = *(__half2*)&v.w;
        }
    }
    float acc[16];
#pragma unroll
    for (int k = 0; k < 16; k++) acc[k] = 0.f;

    const __half2 c02 = __float2half2_rn(0.2f);
    float m = -CUDART_INF_F, den = 0.f;
    int j0 = row[node], j1 = row[node + 1];
    for (int j = j0; j < j1; j++) {
        int s = csrc[j];
        __half2 xl2[8];
        const uint4* lp = (const uint4*)(xlr + (size_t)s * NTOT + fb);
#pragma unroll
        for (int q = 0; q < 2; q++) {
            uint4 v = lp[q];
            xl2[q * 4 + 0] = *(__half2*)&v.x;
            xl2[q * 4 + 1] = *(__half2*)&v.y;
            xl2[q * 4 + 2] = *(__half2*)&v.z;
            xl2[q * 4 + 3] = *(__half2*)&v.w;
        }
        __half2 dot = __float2half2_rn(0.f);
#pragma unroll
        for (int q = 0; q < 8; q++) {
            __half2 t = __hadd2(xl2[q], xr2[q]);
            __half2 l = __hmax2(t, __hmul2(t, c02));
            dot = __hfma2(att2[q], l, dot);
        }
        float2 d2 = __half22float2(dot);
        float p = d2.x + d2.y;
        p += __shfl_xor_sync(0xffffffffu, p, 1);
        p += __shfl_xor_sync(0xffffffffu, p, 2);
        float mn = fmaxf(m, p);
        float scale = __expf(m - mn);
        float w = __expf(p - mn);
        den = den * scale + w;
#pragma unroll
        for (int q = 0; q < 8; q++) {
            float2 f = __half22float2(xl2[q]);
            acc[q * 2 + 0] = acc[q * 2 + 0] * scale + w * f.x;
            acc[q * 2 + 1] = acc[q * 2 + 1] * scale + w * f.y;
        }
        m = mn;
    }
    float inv = 1.f / (den + 1e-16f);
#pragma unroll
    for (int k = 0; k < 16; k++) res[k] = acc[k] * inv;
}

// ---------------- fused agg + GraphNorm + ReLU (layers 1/2), graph-offset capable ----------------
__global__ __launch_bounds__(1024, 1)
void fused_agg_norm_kernel(int goff, const __half* __restrict__ xlr,
                           const int* __restrict__ row, const int* __restrict__ csrc,
                           const float* __restrict__ att, const float* __restrict__ bias,
                           const float* __restrict__ gnw, const float* __restrict__ gnb,
                           const float* __restrict__ gnm, __half* __restrict__ outh) {
    extern __shared__ float stage[];   // [64][512]
    const int g = blockIdx.x + goff;
    const int tid = threadIdx.x, lane = tid & 31, warp = tid >> 5;
    const int fb = ((lane >> 2) << 6) + ((lane & 3) << 4);

    __half2 att2[8];
    {
        const float4* ap = (const float4*)(att + fb);
#pragma unroll
        for (int q = 0; q < 4; q++) {
            float4 a = ap[q];
            att2[q * 2 + 0] = __floats2half2_rn(a.x, a.y);
            att2[q * 2 + 1] = __floats2half2_rn(a.z, a.w);
        }
    }

#pragma unroll
    for (int half = 0; half < 2; half++) {
        int nl = warp + 32 * half;
        int node = g * NPG + nl;
        float res[16];
        agg_node(xlr, node, row, csrc, att2, fb, res);
        float* sp = stage + nl * DD + fb;
#pragma unroll
        for (int q = 0; q < 4; q++) {
            float4 v;
            v.x = res[q * 4 + 0] + bias[fb + q * 4 + 0];
            v.y = res[q * 4 + 1] + bias[fb + q * 4 + 1];
            v.z = res[q * 4 + 2] + bias[fb + q * 4 + 2];
            v.w = res[q * 4 + 3] + bias[fb + q * 4 + 3];
            *(float4*)(sp + q * 4) = v;
        }
    }
    __syncthreads();

    if (tid < DD) {
        const int d = tid;
        float s = 0.f, q = 0.f;
#pragma unroll 8
        for (int i = 0; i < NPG; i++) {
            float x = stage[i * DD + d];
            s += x; q += x * x;
        }
        float mean = s * (1.f / NPG);
        float msm = gnm[d] * mean;
        float v = q * (1.f / NPG) - 2.f * msm * mean + msm * msm;
        float invs = rsqrtf(v + 1e-5f);
        float ww = gnw[d], bb = gnb[d];
        __half* ob = outh + (size_t)g * NPG * DD + d;
#pragma unroll 8
        for (int i = 0; i < NPG; i++) {
            float xc = stage[i * DD + d] - msm;
            float o = fmaxf(ww * xc * invs + bb, 0.f);
            ob[(size_t)i * DD] = __float2half_rn(o);
        }
    }
}

// ---------------- fused agg + norm + pool + linear (layer 3), graph-offset capable ----------------
__global__ __launch_bounds__(1024, 1)
void fused_agg_norm_pool_kernel(int goff, const __half* __restrict__ xlr,
                                const int* __restrict__ row, const int* __restrict__ csrc,
                                const float* __restrict__ att, const float* __restrict__ bias,
                                const float* __restrict__ gnw, const float* __restrict__ gnb,
                                const float* __restrict__ gnm,
                                const float* __restrict__ Wlin, const float* __restrict__ blin,
                                float* __restrict__ out) {
    __shared__ float stage[NPG * FF];
    __shared__ float pool[FF];
    const int g = blockIdx.x + goff;
    const int tid = threadIdx.x, lane = tid & 31, warp = tid >> 5;
    const int fb = ((lane >> 2) << 6) + ((lane & 3) << 4);

    __half2 att2[8];
    {
        const float4* ap = (const float4*)(att + fb);
#pragma unroll
        for (int q = 0; q < 4; q++) {
            float4 a = ap[q];
            att2[q * 2 + 0] = __floats2half2_rn(a.x, a.y);
            att2[q * 2 + 1] = __floats2half2_rn(a.z, a.w);
        }
    }

#pragma unroll
    for (int half = 0; half < 2; half++) {
        int nl = warp + 32 * half;
        int node = g * NPG + nl;
        float r[16];
        agg_node(xlr, node, row, csrc, att2, fb, r);
#pragma unroll
        for (int off = 4; off < 32; off <<= 1)
#pragma unroll
            for (int k = 0; k < 16; k++) r[k] += __shfl_xor_sync(0xffffffffu, r[k], off);
        if (lane < 4) {
            int fo = lane << 4;
#pragma unroll
            for (int k = 0; k < 16; k++)
                stage[nl * FF + fo + k] = r[k] * 0.125f + bias[fo + k];
        }
    }
    __syncthreads();

    if (tid < FF) {
        const int d = tid;
        float s = 0.f, q = 0.f;
#pragma unroll 8
        for (int i = 0; i < NPG; i++) {
            float x = stage[i * FF + d];
            s += x; q += x * x;
        }
        float mean = s * (1.f / NPG);
        float msm = gnm[d] * mean;
        float v = q * (1.f / NPG) - 2.f * msm * mean + msm * msm;
        float invs = rsqrtf(v + 1e-5f);
        float ww = gnw[d], bb = gnb[d];
        float ps = 0.f;
#pragma unroll 8
        for (int i = 0; i < NPG; i++) {
            float xc = stage[i * FF + d] - msm;
            ps += fmaxf(ww * xc * invs + bb, 0.f);
        }
        pool[d] = ps * (1.f / NPG);
    }
    __syncthreads();

    if (tid < 2) {
        float o = blin[tid];
#pragma unroll
        for (int f = 0; f < FF; f++) o += pool[f] * Wlin[f * 2 + tid];
        out[g * 2 + tid] = o;
    }
}

// ---------------- host launcher ----------------
extern "C" void kernel_launch(void* const* d_in, const int* in_sizes, int n_in,
                              void* d_out, int out_size) {
    const float* x     = (const float*)d_in[0];
    const int*   esrc  = (const int*)d_in[1];
    const int*   edst  = (const int*)d_in[2];
    const float* Wl[3]  = {(const float*)d_in[4],  (const float*)d_in[11], (const float*)d_in[18]};
    const float* Wr[3]  = {(const float*)d_in[5],  (const float*)d_in[12], (const float*)d_in[19]};
    const float* att[3] = {(const float*)d_in[6],  (const float*)d_in[13], (const float*)d_in[20]};
    const float* bia[3] = {(const float*)d_in[7],  (const float*)d_in[14], (const float*)d_in[21]};
    const float* gnw[3] = {(const float*)d_in[8],  (const float*)d_in[15], (const float*)d_in[22]};
    const float* gnb[3] = {(const float*)d_in[9],  (const float*)d_in[16], (const float*)d_in[23]};
    const float* gnm[3] = {(const float*)d_in[10], (const float*)d_in[17], (const float*)d_in[24]};
    const float* Wlin = (const float*)d_in[25];
    const float* blin = (const float*)d_in[26];
    float* out = (float*)d_out;

    int E = in_sizes[1];

    __half *X0, *X1, *Xh, *Bh, *Wh;
    int *cnt, *row, *fill, *csrc;
    cudaGetSymbolAddress((void**)&X0,  g_XLR0);
    cudaGetSymbolAddress((void**)&X1,  g_XLR1);
    cudaGetSymbolAddress((void**)&Xh,  g_Xh);
    cudaGetSymbolAddress((void**)&Bh,  g_Bh);
    cudaGetSymbolAddress((void**)&Wh,  g_Wh);
    cudaGetSymbolAddress((void**)&cnt, g_cnt);
    cudaGetSymbolAddress((void**)&row, g_row);
    cudaGetSymbolAddress((void**)&fill,g_fill);
    cudaGetSymbolAddress((void**)&csrc,g_csrc);

    const int FUSED_SMEM = NPG * DD * 4;   // 128 KB
    cudaFuncSetAttribute(fused_agg_norm_kernel,
                         cudaFuncAttributeMaxDynamicSharedMemorySize, FUSED_SMEM);
    cudaFuncSetAttribute(hgemm_kernel,
                         cudaFuncAttributeMaxDynamicSharedMemorySize, GEMM_SMEM);

    cudaStream_t s2;
    cudaStreamCreateWithFlags(&s2, cudaStreamNonBlocking);
    cudaEvent_t eFork, eCSR, eG1, eG2a, eG2b, eG3a, eG3b, eFin;
    cudaEventCreateWithFlags(&eFork, cudaEventDisableTiming);
    cudaEventCreateWithFlags(&eCSR,  cudaEventDisableTiming);
    cudaEventCreateWithFlags(&eG1,   cudaEventDisableTiming);
    cudaEventCreateWithFlags(&eG2a,  cudaEventDisableTiming);
    cudaEventCreateWithFlags(&eG2b,  cudaEventDisableTiming);
    cudaEventCreateWithFlags(&eG3a,  cudaEventDisableTiming);
    cudaEventCreateWithFlags(&eG3b,  cudaEventDisableTiming);
    cudaEventCreateWithFlags(&eFin,  cudaEventDisableTiming);

    __half* WhL[3] = {Wh, Wh + 262144, Wh + 786432};
    dim3 ggridH(NTOT / 128, NN / 256);    // (8, 64): one M-half
    const int HG = GG / 2;                // 128 graphs per half

    // ---- fork: CSR build on s2 ----
    cudaEventRecord(eFork, 0);
    cudaStreamWaitEvent(s2, eFork, 0);
    zero_int_kernel<<<(NN + 255) / 256, 256, 0, s2>>>(cnt, NN);
    count_kernel<<<(E + 255) / 256, 256, 0, s2>>>(edst, E, cnt);
    scan_kernel<<<1, 1024, 0, s2>>>(cnt, row, fill);
    scatter_kernel<<<(E + 255) / 256, 256, 0, s2>>>(esrc, edst, E, fill, csrc);
    cudaEventRecord(eCSR, s2);

    // ---- main: prep + full GEMM1 -> X0 ----
    transpose_all_kernel<<<dim3(16, 16, 6), dim3(32, 8)>>>(
        Wl[0], Wr[0], Wl[1], Wr[1], Wl[2], Wr[2], Wh);
    to_half_kernel<<<(NN * 256 / 4 + 255) / 256, 256>>>((const float4*)x, (__half2*)Xh, NN * 256 / 4);
    hgemm_kernel<<<ggridH, 256, GEMM_SMEM>>>(256, 0,  Xh, WhL[0], X0);
    hgemm_kernel<<<ggridH, 256, GEMM_SMEM>>>(256, 64, Xh, WhL[0], X0);
    cudaEventRecord(eG1, 0);

    // ---- layer-1 agg halves (read X0, write Bh halves) ----
    cudaStreamWaitEvent(0, eCSR, 0);
    fused_agg_norm_kernel<<<HG, 1024, FUSED_SMEM>>>(
        0, X0, row, csrc, att[0], bia[0], gnw[0], gnb[0], gnm[0], Bh);
    cudaStreamWaitEvent(s2, eG1, 0);
    fused_agg_norm_kernel<<<HG, 1024, FUSED_SMEM, s2>>>(
        HG, X0, row, csrc, att[0], bia[0], gnw[0], gnb[0], gnm[0], Bh);

    // ---- layer-2 GEMM halves -> X1 (no WAR: X0 still being read is untouched) ----
    hgemm_kernel<<<ggridH, 256, GEMM_SMEM>>>(512, 0, Bh, WhL[1], X1);
    cudaEventRecord(eG2a, 0);
    hgemm_kernel<<<ggridH, 256, GEMM_SMEM, s2>>>(512, 64, Bh, WhL[1], X1);
    cudaEventRecord(eG2b, s2);

    // ---- layer-2 agg halves (read X1; need BOTH GEMM halves) ----
    cudaStreamWaitEvent(0, eG2b, 0);
    fused_agg_norm_kernel<<<HG, 1024, FUSED_SMEM>>>(
        0, X1, row, csrc, att[1], bia[1], gnw[1], gnb[1], gnm[1], Bh);
    cudaStreamWaitEvent(s2, eG2a, 0);
    fused_agg_norm_kernel<<<HG, 1024, FUSED_SMEM, s2>>>(
        HG, X1, row, csrc, att[1], bia[1], gnw[1], gnb[1], gnm[1], Bh);

    // ---- layer-3 GEMM halves -> X0 (agg1 readers of X0 transitively complete) ----
    hgemm_kernel<<<ggridH, 256, GEMM_SMEM>>>(512, 0, Bh, WhL[2], X0);
    cudaEventRecord(eG3a, 0);
    hgemm_kernel<<<ggridH, 256, GEMM_SMEM, s2>>>(512, 64, Bh, WhL[2], X0);
    cudaEventRecord(eG3b, s2);

    // ---- layer-3 fused agg+norm+pool+linear halves (read X0) ----
    cudaStreamWaitEvent(0, eG3b, 0);
    fused_agg_norm_pool_kernel<<<HG, 1024>>>(
        0, X0, row, csrc, att[2], bia[2], gnw[2], gnb[2], gnm[2], Wlin, blin, out);
    cudaStreamWaitEvent(s2, eG3a, 0);
    fused_agg_norm_pool_kernel<<<HG, 1024, 0, s2>>>(
        HG, X0, row, csrc, att[2], bia[2], gnw[2], gnb[2], gnm[2], Wlin, blin, out);
    cudaEventRecord(eFin, s2);
    cudaStreamWaitEvent(0, eFin, 0);

    cudaEventDestroy(eFork);
    cudaEventDestroy(eCSR);
    cudaEventDestroy(eG1);
    cudaEventDestroy(eG2a);
    cudaEventDestroy(eG2b);
    cudaEventDestroy(eG3a);
    cudaEventDestroy(eG3b);
    cudaStreamDestroy(s2);
    cudaEventDestroy(eFin);
}

// round 14
// speedup vs baseline: 1.0300x; 1.0300x over previous
#include <cuda_runtime.h>
#include <cuda_fp16.h>
#include <math_constants.h>
#include <cstdint>

// ---------------- problem constants ----------------
#define NN 16384      // nodes
#define GG 256        // graphs
#define NPG 64        // nodes per graph
#define FF 64         // per-head features
#define DD 512        // H*F
#define NTOT 1024     // fused Wl|Wr output width
#define EMAX 147456

// ---------------- scratch ----------------
__device__ __half g_XLRh[NN * NTOT];
__device__ __half g_Xh[NN * 256];
__device__ __half g_Bh[NN * DD];
__device__ __half g_Wh[1310720];
__device__ int    g_cnt [NN];
__device__ int    g_row [NN + 1];
__device__ int    g_fill[NN];
__device__ int    g_csrc[EMAX];

// ---------------- helpers ----------------
__device__ __forceinline__ uint32_t smem_u32(const void* p) {
    return (uint32_t)__cvta_generic_to_shared(p);
}
__device__ __forceinline__ void cp16(uint32_t d, const void* s) {
    asm volatile("cp.async.cg.shared.global [%0], [%1], 16;" :: "r"(d), "l"(s));
}

// ---------------- prep kernels ----------------
__global__ void to_half_kernel(const float4* __restrict__ in, __half2* __restrict__ out, int n4) {
    int i = blockIdx.x * blockDim.x + threadIdx.x;
    if (i < n4) {
        float4 v = in[i];
        out[i * 2]     = __floats2half2_rn(v.x, v.y);
        out[i * 2 + 1] = __floats2half2_rn(v.z, v.w);
    }
}

__global__ void transpose_all_kernel(const float* __restrict__ W0, const float* __restrict__ W1,
                                     const float* __restrict__ W2, const float* __restrict__ W3,
                                     const float* __restrict__ W4, const float* __restrict__ W5,
                                     __half* __restrict__ Wh) {
    __shared__ float t[32][33];
    const int z = blockIdx.z;
    const int K = (z < 2) ? 256 : 512;
    const int by = blockIdx.y * 32;
    if (by >= K) return;
    const float* W;
    uint32_t off;
    switch (z) {
        case 0: W = W0; off = 0u;       break;
        case 1: W = W1; off = 131072u;  break;
        case 2: W = W2; off = 262144u;  break;
        case 3: W = W3; off = 524288u;  break;
        case 4: W = W4; off = 786432u;  break;
        default:W = W5; off = 1048576u; break;
    }
    __half* Wt = Wh + off;
    const int bx = blockIdx.x * 32;
    const int x = threadIdx.x, y = threadIdx.y;
#pragma unroll
    for (int j = 0; j < 32; j += 8) t[y + j][x] = W[(size_t)(by + y + j) * DD + bx + x];
    __syncthreads();
#pragma unroll
    for (int j = 0; j < 32; j += 8)
        Wt[(size_t)(bx + y + j) * K + by + x] = __float2half_rn(t[x][y + j]);
}

// ---------------- CSR build ----------------
__global__ void zero_int_kernel(int* p, int n) {
    int i = blockIdx.x * blockDim.x + threadIdx.x;
    if (i < n) p[i] = 0;
}
__global__ void count_kernel(const int* __restrict__ dst, int E, int* __restrict__ cnt) {
    int e = blockIdx.x * blockDim.x + threadIdx.x;
    if (e < E) atomicAdd(&cnt[dst[e]], 1);
}
__global__ void scan_kernel(const int* __restrict__ cnt, int* __restrict__ row,
                            int* __restrict__ fill) {
    __shared__ int s[1024];
    int tid = threadIdx.x;
    int base = tid * 16;
    int local[16];
    int sum = 0;
#pragma unroll
    for (int i = 0; i < 16; i++) { local[i] = sum; sum += cnt[base + i]; }
    s[tid] = sum;
    __syncthreads();
    for (int off = 1; off < 1024; off <<= 1) {
        int v = (tid >= off) ? s[tid - off] : 0;
        __syncthreads();
        s[tid] += v;
        __syncthreads();
    }
    int pre = (tid == 0) ? 0 : s[tid - 1];
#pragma unroll
    for (int i = 0; i < 16; i++) {
        int o = pre + local[i];
        row[base + i]  = o;
        fill[base + i] = o;
    }
    if (tid == 1023) row[NN] = s[1023];
}
__global__ void scatter_kernel(const int* __restrict__ src, const int* __restrict__ dst,
                               int E, int* __restrict__ fill, int* __restrict__ csrc) {
    int e = blockIdx.x * blockDim.x + threadIdx.x;
    if (e < E) {
        int p = atomicAdd(&fill[dst[e]], 1);
        csrc[p] = src[e];
    }
}

// ---------------- persistent fp16 GEMM: C[M,1024] = A[M,K] @ W[1024,K]^T, fp16 out ----------------
// Tile 128x128x32, 256 threads, 8 warps (2m x 4n), warp tile 64x32,
// 3-stage cp.async ring, ONE __syncthreads per K-iter, persistent tile loop.
#define STAGE_BYTES 20480u
#define GEMM_SMEM   (3u * STAGE_BYTES)
#define NTILES      ((NTOT / 128) * (NN / 128))   // 1024
#define GEMM_GRID   296                            // 2 per SM x 148

__global__ __launch_bounds__(256, 2)
void hgemm_kernel(int K, const __half* __restrict__ A,
                  const __half* __restrict__ W, __half* __restrict__ C) {
    extern __shared__ __align__(16) char smem[];
    const uint32_t sb = smem_u32(smem);

    const int tid = threadIdx.x, lane = tid & 31, warp = tid >> 5;
    const int wm = (warp >> 2) << 6;
    const int wn = (warp & 3) << 5;

    const int r = tid >> 1, sc = (tid & 1) << 4;
    const uint32_t dA = sb + (uint32_t)(r * 40 + sc) * 2;
    const uint32_t dB = sb + 10240u + (uint32_t)(r * 40 + sc) * 2;

    const int aRow  = wm + (lane & 15);
    const int aColH = (lane >> 4) << 3;
    const int bRow0 = wn + ((lane >> 4) << 3) + (lane & 7);
    const int bColH = ((lane >> 3) & 1) << 3;
    const int g = lane >> 2, t = lane & 3;
    const int KT = K >> 5;

    for (int tile = blockIdx.x; tile < NTILES; tile += GEMM_GRID) {
        const int bm = (tile >> 3) << 7;   // M tile
        const int bn = (tile & 7) << 7;    // N tile

        // drain previous tile's async + ensure smem free
        asm volatile("cp.async.wait_group 0;" ::: "memory");
        __syncthreads();

        const __half* Ag = A + (size_t)(bm + r) * K + sc;
        const __half* Wg = W + (size_t)(bn + r) * K + sc;

#define LOADSTAGE(s, kt) do {                                    \
        uint32_t _k = (uint32_t)(kt) << 5;                       \
        cp16(dA + (s) * STAGE_BYTES,       Ag + _k);             \
        cp16(dA + (s) * STAGE_BYTES + 16u, Ag + _k + 8);         \
        cp16(dB + (s) * STAGE_BYTES,       Wg + _k);             \
        cp16(dB + (s) * STAGE_BYTES + 16u, Wg + _k + 8);         \
        asm volatile("cp.async.commit_group;" ::: "memory");     \
    } while (0)

        float c[4][4][4] = {};

        LOADSTAGE(0, 0);
        LOADSTAGE(1, 1);

        int s = 0;
        for (int kt = 0; kt < KT; kt++) {
            asm volatile("cp.async.wait_group 1;" ::: "memory");
            __syncthreads();

            if (kt + 2 < KT) {
                int sn = (s + 2 >= 3) ? s - 1 : s + 2;
                LOADSTAGE(sn, kt + 2);
            } else {
                asm volatile("cp.async.commit_group;" ::: "memory");
            }

            const uint32_t aBase = sb + s * STAGE_BYTES;
            const uint32_t bBase = aBase + 10240u;
#pragma unroll
            for (int ks = 0; ks < 2; ks++) {
                uint32_t a[4][4];
#pragma unroll
                for (int mt = 0; mt < 4; mt++) {
                    uint32_t addr = aBase + (uint32_t)((aRow + mt * 16) * 40 + ks * 16 + aColH) * 2;
                    asm volatile("ldmatrix.sync.aligned.m8n8.x4.shared.b16 {%0,%1,%2,%3}, [%4];"
                        : "=r"(a[mt][0]), "=r"(a[mt][1]), "=r"(a[mt][2]), "=r"(a[mt][3])
                        : "r"(addr));
                }
                uint32_t b[2][4];
#pragma unroll
                for (int p = 0; p < 2; p++) {
                    uint32_t addr = bBase + (uint32_t)((bRow0 + p * 16) * 40 + ks * 16 + bColH) * 2;
                    asm volatile("ldmatrix.sync.aligned.m8n8.x4.shared.b16 {%0,%1,%2,%3}, [%4];"
                        : "=r"(b[p][0]), "=r"(b[p][1]), "=r"(b[p][2]), "=r"(b[p][3])
                        : "r"(addr));
                }
#pragma unroll
                for (int mt = 0; mt < 4; mt++)
#pragma unroll
                    for (int nt = 0; nt < 4; nt++) {
                        const uint32_t b0 = b[nt >> 1][(nt & 1) * 2];
                        const uint32_t b1 = b[nt >> 1][(nt & 1) * 2 + 1];
                        asm volatile(
                            "mma.sync.aligned.m16n8k16.row.col.f32.f16.f16.f32 "
                            "{%0,%1,%2,%3},{%4,%5,%6,%7},{%8,%9},{%0,%1,%2,%3};"
                            : "+f"(c[mt][nt][0]), "+f"(c[mt][nt][1]),
                              "+f"(c[mt][nt][2]), "+f"(c[mt][nt][3])
                            : "r"(a[mt][0]), "r"(a[mt][1]), "r"(a[mt][2]), "r"(a[mt][3]),
                              "r"(b0), "r"(b1));
                    }
            }
            s = (s + 1 >= 3) ? 0 : s + 1;
        }
#undef LOADSTAGE

        // epilogue: fp16 output
#pragma unroll
        for (int mt = 0; mt < 4; mt++) {
            int r0 = bm + wm + mt * 16 + g;
#pragma unroll
            for (int nt = 0; nt < 4; nt++) {
                int col = bn + wn + nt * 8 + 2 * t;
                *(__half2*)(C + (size_t)r0 * NTOT + col) =
                    __floats2half2_rn(c[mt][nt][0], c[mt][nt][1]);
                *(__half2*)(C + (size_t)(r0 + 8) * NTOT + col) =
                    __floats2half2_rn(c[mt][nt][2], c[mt][nt][3]);
            }
        }
    }
}

// ---------------- per-warp GATv2 agg for one node (half2 logit path) ----------------
__device__ __forceinline__ void agg_node(const __half* __restrict__ xlr, int node,
                                         const int* __restrict__ row, const int* __restrict__ csrc,
                                         const __half2* att2, int fb, float* res) {
    __half2 xr2[8];
    {
        const uint4* rp = (const uint4*)(xlr + (size_t)node * NTOT + 512 + fb);
#pragma unroll
        for (int q = 0; q < 2; q++) {
            uint4 v = rp[q];
            xr2[q * 4 + 0] = *(__half2*)&v.x;
            xr2[q * 4 + 1] = *(__half2*)&v.y;
            xr2[q * 4 + 2] = *(__half2*)&v.z;
            xr2[q * 4 + 3] = *(__half2*)&v.w;
        }
    }
    float acc[16];
#pragma unroll
    for (int k = 0; k < 16; k++) acc[k] = 0.f;

    const __half2 c02 = __float2half2_rn(0.2f);
    float m = -CUDART_INF_F, den = 0.f;
    int j0 = row[node], j1 = row[node + 1];
    for (int j = j0; j < j1; j++) {
        int s = csrc[j];
        __half2 xl2[8];
        const uint4* lp = (const uint4*)(xlr + (size_t)s * NTOT + fb);
#pragma unroll
        for (int q = 0; q < 2; q++) {
            uint4 v = lp[q];
            xl2[q * 4 + 0] = *(__half2*)&v.x;
            xl2[q * 4 + 1] = *(__half2*)&v.y;
            xl2[q * 4 + 2] = *(__half2*)&v.z;
            xl2[q * 4 + 3] = *(__half2*)&v.w;
        }
        __half2 dot = __float2half2_rn(0.f);
#pragma unroll
        for (int q = 0; q < 8; q++) {
            __half2 t = __hadd2(xl2[q], xr2[q]);
            __half2 l = __hmax2(t, __hmul2(t, c02));
            dot = __hfma2(att2[q], l, dot);
        }
        float2 d2 = __half22float2(dot);
        float p = d2.x + d2.y;
        p += __shfl_xor_sync(0xffffffffu, p, 1);
        p += __shfl_xor_sync(0xffffffffu, p, 2);
        float mn = fmaxf(m, p);
        float scale = __expf(m - mn);
        float w = __expf(p - mn);
        den = den * scale + w;
#pragma unroll
        for (int q = 0; q < 8; q++) {
            float2 f = __half22float2(xl2[q]);
            acc[q * 2 + 0] = acc[q * 2 + 0] * scale + w * f.x;
            acc[q * 2 + 1] = acc[q * 2 + 1] * scale + w * f.y;
        }
        m = mn;
    }
    float inv = 1.f / (den + 1e-16f);
#pragma unroll
    for (int k = 0; k < 16; k++) res[k] = acc[k] * inv;
}

// ---------------- fused agg + GraphNorm + ReLU (layers 1/2) ----------------
__global__ __launch_bounds__(1024, 1)
void fused_agg_norm_kernel(const __half* __restrict__ xlr,
                           const int* __restrict__ row, const int* __restrict__ csrc,
                           const float* __restrict__ att, const float* __restrict__ bias,
                           const float* __restrict__ gnw, const float* __restrict__ gnb,
                           const float* __restrict__ gnm, __half* __restrict__ outh) {
    extern __shared__ float stage[];   // [64][512]
    const int g = blockIdx.x;
    const int tid = threadIdx.x, lane = tid & 31, warp = tid >> 5;
    const int fb = ((lane >> 2) << 6) + ((lane & 3) << 4);

    __half2 att2[8];
    {
        const float4* ap = (const float4*)(att + fb);
#pragma unroll
        for (int q = 0; q < 4; q++) {
            float4 a = ap[q];
            att2[q * 2 + 0] = __floats2half2_rn(a.x, a.y);
            att2[q * 2 + 1] = __floats2half2_rn(a.z, a.w);
        }
    }

#pragma unroll
    for (int half = 0; half < 2; half++) {
        int nl = warp + 32 * half;
        int node = g * NPG + nl;
        float res[16];
        agg_node(xlr, node, row, csrc, att2, fb, res);
        float* sp = stage + nl * DD + fb;
#pragma unroll
        for (int q = 0; q < 4; q++) {
            float4 v;
            v.x = res[q * 4 + 0] + bias[fb + q * 4 + 0];
            v.y = res[q * 4 + 1] + bias[fb + q * 4 + 1];
            v.z = res[q * 4 + 2] + bias[fb + q * 4 + 2];
            v.w = res[q * 4 + 3] + bias[fb + q * 4 + 3];
            *(float4*)(sp + q * 4) = v;
        }
    }
    __syncthreads();

    if (tid < DD) {
        const int d = tid;
        float s = 0.f, q = 0.f;
#pragma unroll 8
        for (int i = 0; i < NPG; i++) {
            float x = stage[i * DD + d];
            s += x; q += x * x;
        }
        float mean = s * (1.f / NPG);
        float msm = gnm[d] * mean;
        float v = q * (1.f / NPG) - 2.f * msm * mean + msm * msm;
        float invs = rsqrtf(v + 1e-5f);
        float ww = gnw[d], bb = gnb[d];
        __half* ob = outh + (size_t)g * NPG * DD + d;
#pragma unroll 8
        for (int i = 0; i < NPG; i++) {
            float xc = stage[i * DD + d] - msm;
            float o = fmaxf(ww * xc * invs + bb, 0.f);
            ob[(size_t)i * DD] = __float2half_rn(o);
        }
    }
}

// ---------------- fused agg + norm + pool + linear (layer 3) ----------------
__global__ __launch_bounds__(1024, 1)
void fused_agg_norm_pool_kernel(const __half* __restrict__ xlr,
                                const int* __restrict__ row, const int* __restrict__ csrc,
                                const float* __restrict__ att, const float* __restrict__ bias,
                                const float* __restrict__ gnw, const float* __restrict__ gnb,
                                const float* __restrict__ gnm,
                                const float* __restrict__ Wlin, const float* __restrict__ blin,
                                float* __restrict__ out) {
    __shared__ float stage[NPG * FF];
    __shared__ float pool[FF];
    const int g = blockIdx.x;
    const int tid = threadIdx.x, lane = tid & 31, warp = tid >> 5;
    const int fb = ((lane >> 2) << 6) + ((lane & 3) << 4);

    __half2 att2[8];
    {
        const float4* ap = (const float4*)(att + fb);
#pragma unroll
        for (int q = 0; q < 4; q++) {
            float4 a = ap[q];
            att2[q * 2 + 0] = __floats2half2_rn(a.x, a.y);
            att2[q * 2 + 1] = __floats2half2_rn(a.z, a.w);
        }
    }

#pragma unroll
    for (int half = 0; half < 2; half++) {
        int nl = warp + 32 * half;
        int node = g * NPG + nl;
        float r[16];
        agg_node(xlr, node, row, csrc, att2, fb, r);
#pragma unroll
        for (int off = 4; off < 32; off <<= 1)
#pragma unroll
            for (int k = 0; k < 16; k++) r[k] += __shfl_xor_sync(0xffffffffu, r[k], off);
        if (lane < 4) {
            int fo = lane << 4;
#pragma unroll
            for (int k = 0; k < 16; k++)
                stage[nl * FF + fo + k] = r[k] * 0.125f + bias[fo + k];
        }
    }
    __syncthreads();

    if (tid < FF) {
        const int d = tid;
        float s = 0.f, q = 0.f;
#pragma unroll 8
        for (int i = 0; i < NPG; i++) {
            float x = stage[i * FF + d];
            s += x; q += x * x;
        }
        float mean = s * (1.f / NPG);
        float msm = gnm[d] * mean;
        float v = q * (1.f / NPG) - 2.f * msm * mean + msm * msm;
        float invs = rsqrtf(v + 1e-5f);
        float ww = gnw[d], bb = gnb[d];
        float ps = 0.f;
#pragma unroll 8
        for (int i = 0; i < NPG; i++) {
            float xc = stage[i * FF + d] - msm;
            ps += fmaxf(ww * xc * invs + bb, 0.f);
        }
        pool[d] = ps * (1.f / NPG);
    }
    __syncthreads();

    if (tid < 2) {
        float o = blin[tid];
#pragma unroll
        for (int f = 0; f < FF; f++) o += pool[f] * Wlin[f * 2 + tid];
        out[g * 2 + tid] = o;
    }
}

// ---------------- host launcher ----------------
extern "C" void kernel_launch(void* const* d_in, const int* in_sizes, int n_in,
                              void* d_out, int out_size) {
    const float* x     = (const float*)d_in[0];
    const int*   esrc  = (const int*)d_in[1];
    const int*   edst  = (const int*)d_in[2];
    const float* Wl[3]  = {(const float*)d_in[4],  (const float*)d_in[11], (const float*)d_in[18]};
    const float* Wr[3]  = {(const float*)d_in[5],  (const float*)d_in[12], (const float*)d_in[19]};
    const float* att[3] = {(const float*)d_in[6],  (const float*)d_in[13], (const float*)d_in[20]};
    const float* bia[3] = {(const float*)d_in[7],  (const float*)d_in[14], (const float*)d_in[21]};
    const float* gnw[3] = {(const float*)d_in[8],  (const float*)d_in[15], (const float*)d_in[22]};
    const float* gnb[3] = {(const float*)d_in[9],  (const float*)d_in[16], (const float*)d_in[23]};
    const float* gnm[3] = {(const float*)d_in[10], (const float*)d_in[17], (const float*)d_in[24]};
    const float* Wlin = (const float*)d_in[25];
    const float* blin = (const float*)d_in[26];
    float* out = (float*)d_out;

    int E = in_sizes[1];

    __half *XLRh, *Xh, *Bh, *Wh;
    int *cnt, *row, *fill, *csrc;
    cudaGetSymbolAddress((void**)&XLRh, g_XLRh);
    cudaGetSymbolAddress((void**)&Xh,   g_Xh);
    cudaGetSymbolAddress((void**)&Bh,   g_Bh);
    cudaGetSymbolAddress((void**)&Wh,   g_Wh);
    cudaGetSymbolAddress((void**)&cnt,  g_cnt);
    cudaGetSymbolAddress((void**)&row,  g_row);
    cudaGetSymbolAddress((void**)&fill, g_fill);
    cudaGetSymbolAddress((void**)&csrc, g_csrc);

    const int FUSED_SMEM = NPG * DD * 4;   // 128 KB
    cudaFuncSetAttribute(fused_agg_norm_kernel,
                         cudaFuncAttributeMaxDynamicSharedMemorySize, FUSED_SMEM);
    cudaFuncSetAttribute(hgemm_kernel,
                         cudaFuncAttributeMaxDynamicSharedMemorySize, GEMM_SMEM);

    // ---- fork CSR build onto a side stream ----
    cudaStream_t s2;
    cudaStreamCreateWithFlags(&s2, cudaStreamNonBlocking);
    cudaEvent_t e1, e2;
    cudaEventCreateWithFlags(&e1, cudaEventDisableTiming);
    cudaEventCreateWithFlags(&e2, cudaEventDisableTiming);

    cudaEventRecord(e1, 0);
    cudaStreamWaitEvent(s2, e1, 0);
    zero_int_kernel<<<(NN + 255) / 256, 256, 0, s2>>>(cnt, NN);
    count_kernel<<<(E + 255) / 256, 256, 0, s2>>>(edst, E, cnt);
    scan_kernel<<<1, 1024, 0, s2>>>(cnt, row, fill);
    scatter_kernel<<<(E + 255) / 256, 256, 0, s2>>>(esrc, edst, E, fill, csrc);
    cudaEventRecord(e2, s2);

    // ---- main stream: prep + layer 1 GEMM ----
    transpose_all_kernel<<<dim3(16, 16, 6), dim3(32, 8)>>>(
        Wl[0], Wr[0], Wl[1], Wr[1], Wl[2], Wr[2], Wh);
    to_half_kernel<<<(NN * 256 / 4 + 255) / 256, 256>>>((const float4*)x, (__half2*)Xh, NN * 256 / 4);

    __half* WhL[3] = {Wh, Wh + 262144, Wh + 786432};

    hgemm_kernel<<<GEMM_GRID, 256, GEMM_SMEM>>>(256, Xh, WhL[0], XLRh);

    // join: agg needs the CSR
    cudaStreamWaitEvent(0, e2, 0);

    fused_agg_norm_kernel<<<GG, 1024, FUSED_SMEM>>>(
        XLRh, row, csrc, att[0], bia[0], gnw[0], gnb[0], gnm[0], Bh);

    // layer 2
    hgemm_kernel<<<GEMM_GRID, 256, GEMM_SMEM>>>(512, Bh, WhL[1], XLRh);
    fused_agg_norm_kernel<<<GG, 1024, FUSED_SMEM>>>(
        XLRh, row, csrc, att[1], bia[1], gnw[1], gnb[1], gnm[1], Bh);

    // layer 3 + pool + linear
    hgemm_kernel<<<GEMM_GRID, 256, GEMM_SMEM>>>(512, Bh, WhL[2], XLRh);
    fused_agg_norm_pool_kernel<<<GG, 1024>>>(
        XLRh, row, csrc, att[2], bia[2], gnw[2], gnb[2], gnm[2], Wlin, blin, out);

    cudaEventDestroy(e1);
    cudaEventDestroy(e2);
    cudaStreamDestroy(s2);
}

// round 16
// speedup vs baseline: 1.0732x; 1.0420x over previous
#include <cuda_runtime.h>
#include <cuda_fp16.h>
#include <math_constants.h>
#include <cstdint>

// ---------------- problem constants ----------------
#define NN 16384      // nodes
#define GG 256        // graphs
#define NPG 64        // nodes per graph
#define FF 64         // per-head features
#define DD 512        // H*F
#define NTOT 1024     // fused Wl|Wr output width
#define EMAX 147456

// ---------------- scratch ----------------
__device__ __half g_XLRh[NN * NTOT];
__device__ __half g_Xh[NN * 256];
__device__ __half g_Bh[NN * DD];
__device__ __half g_Wh[1310720];
__device__ int    g_cnt [NN];
__device__ int    g_row [NN + 1];
__device__ int    g_fill[NN];
__device__ int    g_csrc[EMAX];

// ---------------- helpers ----------------
__device__ __forceinline__ uint32_t smem_u32(const void* p) {
    return (uint32_t)__cvta_generic_to_shared(p);
}
__device__ __forceinline__ void cp16(uint32_t d, const void* s) {
    asm volatile("cp.async.cg.shared.global [%0], [%1], 16;" :: "r"(d), "l"(s));
}

// ---------------- prep kernels ----------------
__global__ void to_half_kernel(const float4* __restrict__ in, __half2* __restrict__ out, int n4) {
    int i = blockIdx.x * blockDim.x + threadIdx.x;
    if (i < n4) {
        float4 v = in[i];
        out[i * 2]     = __floats2half2_rn(v.x, v.y);
        out[i * 2 + 1] = __floats2half2_rn(v.z, v.w);
    }
}

__global__ void transpose_all_kernel(const float* __restrict__ W0, const float* __restrict__ W1,
                                     const float* __restrict__ W2, const float* __restrict__ W3,
                                     const float* __restrict__ W4, const float* __restrict__ W5,
                                     __half* __restrict__ Wh) {
    __shared__ float t[32][33];
    const int z = blockIdx.z;
    const int K = (z < 2) ? 256 : 512;
    const int by = blockIdx.y * 32;
    if (by >= K) return;
    const float* W;
    uint32_t off;
    switch (z) {
        case 0: W = W0; off = 0u;       break;
        case 1: W = W1; off = 131072u;  break;
        case 2: W = W2; off = 262144u;  break;
        case 3: W = W3; off = 524288u;  break;
        case 4: W = W4; off = 786432u;  break;
        default:W = W5; off = 1048576u; break;
    }
    __half* Wt = Wh + off;
    const int bx = blockIdx.x * 32;
    const int x = threadIdx.x, y = threadIdx.y;
#pragma unroll
    for (int j = 0; j < 32; j += 8) t[y + j][x] = W[(size_t)(by + y + j) * DD + bx + x];
    __syncthreads();
#pragma unroll
    for (int j = 0; j < 32; j += 8)
        Wt[(size_t)(bx + y + j) * K + by + x] = __float2half_rn(t[x][y + j]);
}

// ---------------- CSR build ----------------
__global__ void zero_int_kernel(int* p, int n) {
    int i = blockIdx.x * blockDim.x + threadIdx.x;
    if (i < n) p[i] = 0;
}
__global__ void count_kernel(const int* __restrict__ dst, int E, int* __restrict__ cnt) {
    int e = blockIdx.x * blockDim.x + threadIdx.x;
    if (e < E) atomicAdd(&cnt[dst[e]], 1);
}
__global__ void scan_kernel(const int* __restrict__ cnt, int* __restrict__ row,
                            int* __restrict__ fill) {
    __shared__ int s[1024];
    int tid = threadIdx.x;
    int base = tid * 16;
    int local[16];
    int sum = 0;
#pragma unroll
    for (int i = 0; i < 16; i++) { local[i] = sum; sum += cnt[base + i]; }
    s[tid] = sum;
    __syncthreads();
    for (int off = 1; off < 1024; off <<= 1) {
        int v = (tid >= off) ? s[tid - off] : 0;
        __syncthreads();
        s[tid] += v;
        __syncthreads();
    }
    int pre = (tid == 0) ? 0 : s[tid - 1];
#pragma unroll
    for (int i = 0; i < 16; i++) {
        int o = pre + local[i];
        row[base + i]  = o;
        fill[base + i] = o;
    }
    if (tid == 1023) row[NN] = s[1023];
}
__global__ void scatter_kernel(const int* __restrict__ src, const int* __restrict__ dst,
                               int E, int* __restrict__ fill, int* __restrict__ csrc) {
    int e = blockIdx.x * blockDim.x + threadIdx.x;
    if (e < E) {
        int p = atomicAdd(&fill[dst[e]], 1);
        csrc[p] = src[e];
    }
}

// ---------------- fp16 GEMM: C[M,1024] = A[M,K] @ W[1024,K]^T, fp16 out ----------------
// CTA tile 128x128x32, 256 threads, 8 warps (2m x 4n), warp tile 64x32,
// 3-stage cp.async ring with ONE __syncthreads per K-iter. (round-11 best config)
#define STAGE_BYTES 20480u
#define GEMM_SMEM   (3u * STAGE_BYTES)

__global__ __launch_bounds__(256, 2)
void hgemm_kernel(int K, const __half* __restrict__ A,
                  const __half* __restrict__ W, __half* __restrict__ C) {
    extern __shared__ __align__(16) char smem[];
    const uint32_t sb = smem_u32(smem);

    const int tid = threadIdx.x, lane = tid & 31, warp = tid >> 5;
    const int wm = (warp >> 2) << 6;
    const int wn = (warp & 3) << 5;
    const int bm = blockIdx.y << 7, bn = blockIdx.x << 7;

    const int r = tid >> 1, sc = (tid & 1) << 4;
    const __half* Ag = A + (size_t)(bm + r) * K + sc;
    const __half* Wg = W + (size_t)(bn + r) * K + sc;
    const uint32_t dA = sb + (uint32_t)(r * 40 + sc) * 2;
    const uint32_t dB = sb + 10240u + (uint32_t)(r * 40 + sc) * 2;

#define LOADSTAGE(s, kt) do {                                    \
        uint32_t _k = (uint32_t)(kt) << 5;                       \
        cp16(dA + (s) * STAGE_BYTES,       Ag + _k);             \
        cp16(dA + (s) * STAGE_BYTES + 16u, Ag + _k + 8);         \
        cp16(dB + (s) * STAGE_BYTES,       Wg + _k);             \
        cp16(dB + (s) * STAGE_BYTES + 16u, Wg + _k + 8);         \
        asm volatile("cp.async.commit_group;" ::: "memory");     \
    } while (0)

    float c[4][4][4] = {};

    const int aRow  = wm + (lane & 15);
    const int aColH = (lane >> 4) << 3;
    const int bRow0 = wn + ((lane >> 4) << 3) + (lane & 7);
    const int bColH = ((lane >> 3) & 1) << 3;

    LOADSTAGE(0, 0);
    LOADSTAGE(1, 1);

    const int KT = K >> 5;
    int s = 0;
    for (int kt = 0; kt < KT; kt++) {
        asm volatile("cp.async.wait_group 1;" ::: "memory");
        __syncthreads();

        if (kt + 2 < KT) {
            int sn = (s + 2 >= 3) ? s - 1 : s + 2;
            LOADSTAGE(sn, kt + 2);
        } else {
            asm volatile("cp.async.commit_group;" ::: "memory");
        }

        const uint32_t aBase = sb + s * STAGE_BYTES;
        const uint32_t bBase = aBase + 10240u;
#pragma unroll
        for (int ks = 0; ks < 2; ks++) {
            uint32_t a[4][4];
#pragma unroll
            for (int mt = 0; mt < 4; mt++) {
                uint32_t addr = aBase + (uint32_t)((aRow + mt * 16) * 40 + ks * 16 + aColH) * 2;
                asm volatile("ldmatrix.sync.aligned.m8n8.x4.shared.b16 {%0,%1,%2,%3}, [%4];"
                    : "=r"(a[mt][0]), "=r"(a[mt][1]), "=r"(a[mt][2]), "=r"(a[mt][3])
                    : "r"(addr));
            }
            uint32_t b[2][4];
#pragma unroll
            for (int p = 0; p < 2; p++) {
                uint32_t addr = bBase + (uint32_t)((bRow0 + p * 16) * 40 + ks * 16 + bColH) * 2;
                asm volatile("ldmatrix.sync.aligned.m8n8.x4.shared.b16 {%0,%1,%2,%3}, [%4];"
                    : "=r"(b[p][0]), "=r"(b[p][1]), "=r"(b[p][2]), "=r"(b[p][3])
                    : "r"(addr));
            }
#pragma unroll
            for (int mt = 0; mt < 4; mt++)
#pragma unroll
                for (int nt = 0; nt < 4; nt++) {
                    const uint32_t b0 = b[nt >> 1][(nt & 1) * 2];
                    const uint32_t b1 = b[nt >> 1][(nt & 1) * 2 + 1];
                    asm volatile(
                        "mma.sync.aligned.m16n8k16.row.col.f32.f16.f16.f32 "
                        "{%0,%1,%2,%3},{%4,%5,%6,%7},{%8,%9},{%0,%1,%2,%3};"
                        : "+f"(c[mt][nt][0]), "+f"(c[mt][nt][1]),
                          "+f"(c[mt][nt][2]), "+f"(c[mt][nt][3])
                        : "r"(a[mt][0]), "r"(a[mt][1]), "r"(a[mt][2]), "r"(a[mt][3]),
                          "r"(b0), "r"(b1));
                }
        }
        s = (s + 1 >= 3) ? 0 : s + 1;
    }
#undef LOADSTAGE

    const int g = lane >> 2, t = lane & 3;
#pragma unroll
    for (int mt = 0; mt < 4; mt++) {
        int r0 = bm + wm + mt * 16 + g;
#pragma unroll
        for (int nt = 0; nt < 4; nt++) {
            int col = bn + wn + nt * 8 + 2 * t;
            *(__half2*)(C + (size_t)r0 * NTOT + col) =
                __floats2half2_rn(c[mt][nt][0], c[mt][nt][1]);
            *(__half2*)(C + (size_t)(r0 + 8) * NTOT + col) =
                __floats2half2_rn(c[mt][nt][2], c[mt][nt][3]);
        }
    }
}

// ---------------- per-warp GATv2 agg for one node (half2 logit path) ----------------
__device__ __forceinline__ void agg_node(const __half* __restrict__ xlr, int node,
                                         const int* __restrict__ row, const int* __restrict__ csrc,
                                         const __half2* att2, int fb, float* res) {
    __half2 xr2[8];
    {
        const uint4* rp = (const uint4*)(xlr + (size_t)node * NTOT + 512 + fb);
#pragma unroll
        for (int q = 0; q < 2; q++) {
            uint4 v = rp[q];
            xr2[q * 4 + 0] = *(__half2*)&v.x;
            xr2[q * 4 + 1] = *(__half2*)&v.y;
            xr2[q * 4 + 2] = *(__half2*)&v.z;
            xr2[q * 4 + 3] = *(__half2*)&v.w;
        }
    }
    float acc[16];
#pragma unroll
    for (int k = 0; k < 16; k++) acc[k] = 0.f;

    const __half2 c02 = __float2half2_rn(0.2f);
    float m = -CUDART_INF_F, den = 0.f;
    int j0 = row[node], j1 = row[node + 1];
    for (int j = j0; j < j1; j++) {
        int s = csrc[j];
        __half2 xl2[8];
        const uint4* lp = (const uint4*)(xlr + (size_t)s * NTOT + fb);
#pragma unroll
        for (int q = 0; q < 2; q++) {
            uint4 v = lp[q];
            xl2[q * 4 + 0] = *(__half2*)&v.x;
            xl2[q * 4 + 1] = *(__half2*)&v.y;
            xl2[q * 4 + 2] = *(__half2*)&v.z;
            xl2[q * 4 + 3] = *(__half2*)&v.w;
        }
        __half2 dot = __float2half2_rn(0.f);
#pragma unroll
        for (int q = 0; q < 8; q++) {
            __half2 t = __hadd2(xl2[q], xr2[q]);
            __half2 l = __hmax2(t, __hmul2(t, c02));
            dot = __hfma2(att2[q], l, dot);
        }
        float2 d2 = __half22float2(dot);
        float p = d2.x + d2.y;
        p += __shfl_xor_sync(0xffffffffu, p, 1);
        p += __shfl_xor_sync(0xffffffffu, p, 2);
        float mn = fmaxf(m, p);
        float scale = __expf(m - mn);
        float w = __expf(p - mn);
        den = den * scale + w;
#pragma unroll
        for (int q = 0; q < 8; q++) {
            float2 f = __half22float2(xl2[q]);
            acc[q * 2 + 0] = acc[q * 2 + 0] * scale + w * f.x;
            acc[q * 2 + 1] = acc[q * 2 + 1] * scale + w * f.y;
        }
        m = mn;
    }
    float inv = 1.f / (den + 1e-16f);
#pragma unroll
    for (int k = 0; k < 16; k++) res[k] = acc[k] * inv;
}

// ---------------- fused agg + GraphNorm + ReLU (layers 1/2) ----------------
// 512 threads, 16 warps x 4 nodes, fp16 staging (64 KB) -> 2 blocks/SM, no wave tail.
__global__ __launch_bounds__(512, 2)
void fused_agg_norm_kernel(const __half* __restrict__ xlr,
                           const int* __restrict__ row, const int* __restrict__ csrc,
                           const float* __restrict__ att, const float* __restrict__ bias,
                           const float* __restrict__ gnw, const float* __restrict__ gnb,
                           const float* __restrict__ gnm, __half* __restrict__ outh) {
    extern __shared__ __half hstage[];   // [64][512] fp16 = 64 KB
    const int g = blockIdx.x;
    const int tid = threadIdx.x, lane = tid & 31, warp = tid >> 5;  // warp 0..15
    const int fb = ((lane >> 2) << 6) + ((lane & 3) << 4);

    __half2 att2[8];
    {
        const float4* ap = (const float4*)(att + fb);
#pragma unroll
        for (int q = 0; q < 4; q++) {
            float4 a = ap[q];
            att2[q * 2 + 0] = __floats2half2_rn(a.x, a.y);
            att2[q * 2 + 1] = __floats2half2_rn(a.z, a.w);
        }
    }

#pragma unroll
    for (int quarter = 0; quarter < 4; quarter++) {
        int nl = warp + 16 * quarter;
        int node = g * NPG + nl;
        float res[16];
        agg_node(xlr, node, row, csrc, att2, fb, res);
        uint32_t h2[8];
#pragma unroll
        for (int q = 0; q < 8; q++) {
            __half2 hv = __floats2half2_rn(res[q * 2] + bias[fb + q * 2],
                                           res[q * 2 + 1] + bias[fb + q * 2 + 1]);
            h2[q] = *(uint32_t*)&hv;
        }
        uint4* sp = (uint4*)(hstage + nl * DD + fb);
        sp[0] = make_uint4(h2[0], h2[1], h2[2], h2[3]);
        sp[1] = make_uint4(h2[4], h2[5], h2[6], h2[7]);
    }
    __syncthreads();

    {
        const int d = tid;   // 512 threads = 512 columns
        float s = 0.f, q = 0.f;
#pragma unroll 8
        for (int i = 0; i < NPG; i++) {
            float x = __half2float(hstage[i * DD + d]);
            s += x; q += x * x;
        }
        float mean = s * (1.f / NPG);
        float msm = gnm[d] * mean;
        float v = q * (1.f / NPG) - 2.f * msm * mean + msm * msm;
        float invs = rsqrtf(v + 1e-5f);
        float ww = gnw[d], bb = gnb[d];
        __half* ob = outh + (size_t)g * NPG * DD + d;
#pragma unroll 8
        for (int i = 0; i < NPG; i++) {
            float xc = __half2float(hstage[i * DD + d]) - msm;
            float o = fmaxf(ww * xc * invs + bb, 0.f);
            ob[(size_t)i * DD] = __float2half_rn(o);
        }
    }
}

// ---------------- fused agg + norm + pool + linear (layer 3), 512 threads ----------------
__global__ __launch_bounds__(512, 2)
void fused_agg_norm_pool_kernel(const __half* __restrict__ xlr,
                                const int* __restrict__ row, const int* __restrict__ csrc,
                                const float* __restrict__ att, const float* __restrict__ bias,
                                const float* __restrict__ gnw, const float* __restrict__ gnb,
                                const float* __restrict__ gnm,
                                const float* __restrict__ Wlin, const float* __restrict__ blin,
                                float* __restrict__ out) {
    __shared__ float stage[NPG * FF];   // 16 KB
    __shared__ float pool[FF];
    const int g = blockIdx.x;
    const int tid = threadIdx.x, lane = tid & 31, warp = tid >> 5;  // 0..15
    const int fb = ((lane >> 2) << 6) + ((lane & 3) << 4);

    __half2 att2[8];
    {
        const float4* ap = (const float4*)(att + fb);
#pragma unroll
        for (int q = 0; q < 4; q++) {
            float4 a = ap[q];
            att2[q * 2 + 0] = __floats2half2_rn(a.x, a.y);
            att2[q * 2 + 1] = __floats2half2_rn(a.z, a.w);
        }
    }

#pragma unroll
    for (int quarter = 0; quarter < 4; quarter++) {
        int nl = warp + 16 * quarter;
        int node = g * NPG + nl;
        float r[16];
        agg_node(xlr, node, row, csrc, att2, fb, r);
#pragma unroll
        for (int off = 4; off < 32; off <<= 1)
#pragma unroll
            for (int k = 0; k < 16; k++) r[k] += __shfl_xor_sync(0xffffffffu, r[k], off);
        if (lane < 4) {
            int fo = lane << 4;
#pragma unroll
            for (int k = 0; k < 16; k++)
                stage[nl * FF + fo + k] = r[k] * 0.125f + bias[fo + k];
        }
    }
    __syncthreads();

    if (tid < FF) {
        const int d = tid;
        float s = 0.f, q = 0.f;
#pragma unroll 8
        for (int i = 0; i < NPG; i++) {
            float x = stage[i * FF + d];
            s += x; q += x * x;
        }
        float mean = s * (1.f / NPG);
        float msm = gnm[d] * mean;
        float v = q * (1.f / NPG) - 2.f * msm * mean + msm * msm;
        float invs = rsqrtf(v + 1e-5f);
        float ww = gnw[d], bb = gnb[d];
        float ps = 0.f;
#pragma unroll 8
        for (int i = 0; i < NPG; i++) {
            float xc = stage[i * FF + d] - msm;
            ps += fmaxf(ww * xc * invs + bb, 0.f);
        }
        pool[d] = ps * (1.f / NPG);
    }
    __syncthreads();

    if (tid < 2) {
        float o = blin[tid];
#pragma unroll
        for (int f = 0; f < FF; f++) o += pool[f] * Wlin[f * 2 + tid];
        out[g * 2 + tid] = o;
    }
}

// ---------------- host launcher ----------------
extern "C" void kernel_launch(void* const* d_in, const int* in_sizes, int n_in,
                              void* d_out, int out_size) {
    const float* x     = (const float*)d_in[0];
    const int*   esrc  = (const int*)d_in[1];
    const int*   edst  = (const int*)d_in[2];
    const float* Wl[3]  = {(const float*)d_in[4],  (const float*)d_in[11], (const float*)d_in[18]};
    const float* Wr[3]  = {(const float*)d_in[5],  (const float*)d_in[12], (const float*)d_in[19]};
    const float* att[3] = {(const float*)d_in[6],  (const float*)d_in[13], (const float*)d_in[20]};
    const float* bia[3] = {(const float*)d_in[7],  (const float*)d_in[14], (const float*)d_in[21]};
    const float* gnw[3] = {(const float*)d_in[8],  (const float*)d_in[15], (const float*)d_in[22]};
    const float* gnb[3] = {(const float*)d_in[9],  (const float*)d_in[16], (const float*)d_in[23]};
    const float* gnm[3] = {(const float*)d_in[10], (const float*)d_in[17], (const float*)d_in[24]};
    const float* Wlin = (const float*)d_in[25];
    const float* blin = (const float*)d_in[26];
    float* out = (float*)d_out;

    int E = in_sizes[1];

    __half *XLRh, *Xh, *Bh, *Wh;
    int *cnt, *row, *fill, *csrc;
    cudaGetSymbolAddress((void**)&XLRh, g_XLRh);
    cudaGetSymbolAddress((void**)&Xh,   g_Xh);
    cudaGetSymbolAddress((void**)&Bh,   g_Bh);
    cudaGetSymbolAddress((void**)&Wh,   g_Wh);
    cudaGetSymbolAddress((void**)&cnt,  g_cnt);
    cudaGetSymbolAddress((void**)&row,  g_row);
    cudaGetSymbolAddress((void**)&fill, g_fill);
    cudaGetSymbolAddress((void**)&csrc, g_csrc);

    const int FUSED_SMEM = NPG * DD * 2;   // 64 KB fp16 staging
    cudaFuncSetAttribute(fused_agg_norm_kernel,
                         cudaFuncAttributeMaxDynamicSharedMemorySize, FUSED_SMEM);
    cudaFuncSetAttribute(hgemm_kernel,
                         cudaFuncAttributeMaxDynamicSharedMemorySize, GEMM_SMEM);

    // ---- fork CSR build onto a side stream ----
    cudaStream_t s2;
    cudaStreamCreateWithFlags(&s2, cudaStreamNonBlocking);
    cudaEvent_t e1, e2;
    cudaEventCreateWithFlags(&e1, cudaEventDisableTiming);
    cudaEventCreateWithFlags(&e2, cudaEventDisableTiming);

    cudaEventRecord(e1, 0);
    cudaStreamWaitEvent(s2, e1, 0);
    zero_int_kernel<<<(NN + 255) / 256, 256, 0, s2>>>(cnt, NN);
    count_kernel<<<(E + 255) / 256, 256, 0, s2>>>(edst, E, cnt);
    scan_kernel<<<1, 1024, 0, s2>>>(cnt, row, fill);
    scatter_kernel<<<(E + 255) / 256, 256, 0, s2>>>(esrc, edst, E, fill, csrc);
    cudaEventRecord(e2, s2);

    // ---- main stream: prep + layer 1 GEMM ----
    transpose_all_kernel<<<dim3(16, 16, 6), dim3(32, 8)>>>(
        Wl[0], Wr[0], Wl[1], Wr[1], Wl[2], Wr[2], Wh);
    to_half_kernel<<<(NN * 256 / 4 + 255) / 256, 256>>>((const float4*)x, (__half2*)Xh, NN * 256 / 4);

    __half* WhL[3] = {Wh, Wh + 262144, Wh + 786432};
    dim3 ggrid(NTOT / 128, NN / 128);     // (8, 128)

    hgemm_kernel<<<ggrid, 256, GEMM_SMEM>>>(256, Xh, WhL[0], XLRh);

    // join: agg needs the CSR
    cudaStreamWaitEvent(0, e2, 0);

    fused_agg_norm_kernel<<<GG, 512, FUSED_SMEM>>>(
        XLRh, row, csrc, att[0], bia[0], gnw[0], gnb[0], gnm[0], Bh);

    // layer 2
    hgemm_kernel<<<ggrid, 256, GEMM_SMEM>>>(512, Bh, WhL[1], XLRh);
    fused_agg_norm_kernel<<<GG, 512, FUSED_SMEM>>>(
        XLRh, row, csrc, att[1], bia[1], gnw[1], gnb[1], gnm[1], Bh);

    // layer 3 + pool + linear
    hgemm_kernel<<<ggrid, 256, GEMM_SMEM>>>(512, Bh, WhL[2], XLRh);
    fused_agg_norm_pool_kernel<<<GG, 512>>>(
        XLRh, row, csrc, att[2], bia[2], gnw[2], gnb[2], gnm[2], Wlin, blin, out);

    cudaEventDestroy(e1);
    cudaEventDestroy(e2);
    cudaStreamDestroy(s2);
}